// round 14
// baseline (speedup 1.0000x reference)
#include <cuda_runtime.h>
#include <cstdint>

// CTC loss (scaled forward algorithm, linear domain).
// B=512, T=512, C=256, L=64, S=129, blank = C-1.
// 148 blocks x 4 warps: warp w of block i processes batch b = w*148+i
// (b >= 512 -> idle), so all 148 SMs' TMA/L1TEX slices carry streams.
// Per warp: private 3-stage x 16-row TMA ring (48KB), lane-major state map
// s = 5*lane + k (2 shuffles/step), REDUX exact pow-2 rescale per 4 steps
// (lagged one group, target biased 2^40). Last chunk peeled.
// NEW: cp.async.bulk.prefetch.L2 stages chunk c+NSTG+PFD into L2 (bulk
// path, 1 instr/chunk) so ring TMA completes from L2, not DRAM.

#define TT 512
#define CC 256
#define BB 512
#define LL 64
#define SS 129
#define EPSF 1e-7f
#define RPC 16                 // rows (timesteps) per stage
#define NSTG 3                 // ring stages per warp
#define NCH 32                 // chunks covering t = 1 .. 511 (last is short)
#define WPB 4                  // warps per block
#define GRID 148
#define PFD 4                  // L2 bulk-prefetch distance beyond the ring
#define STAGE_FLOATS (RPC * CC)
#define WARP_FLOATS (NSTG * STAGE_FLOATS)
#define SMEM_BYTES (WPB * WARP_FLOATS * 4 + WPB * NSTG * 8 + 16)

__device__ __forceinline__ uint32_t smem_u32(const void* p) {
    uint32_t a;
    asm("{ .reg .u64 t; cvta.to.shared.u64 t, %1; cvt.u32.u64 %0, t; }"
        : "=r"(a) : "l"(p));
    return a;
}
__device__ __forceinline__ void mbar_init(uint32_t addr, uint32_t cnt) {
    asm volatile("mbarrier.init.shared.b64 [%0], %1;" :: "r"(addr), "r"(cnt) : "memory");
}
__device__ __forceinline__ void mbar_expect_tx(uint32_t addr, uint32_t bytes) {
    asm volatile("mbarrier.arrive.expect_tx.shared.b64 _, [%0], %1;"
                 :: "r"(addr), "r"(bytes) : "memory");
}
__device__ __forceinline__ void mbar_wait(uint32_t addr, uint32_t parity) {
    asm volatile(
        "{\n\t.reg .pred P;\n\t"
        "LAB_WAIT_%=:\n\t"
        "mbarrier.try_wait.parity.acquire.cta.shared::cta.b64 P, [%0], %1, 0x989680;\n\t"
        "@P bra.uni LAB_DONE_%=;\n\t"
        "bra.uni LAB_WAIT_%=;\n\t"
        "LAB_DONE_%=:\n\t}"
        :: "r"(addr), "r"(parity) : "memory");
}
__device__ __forceinline__ void bulk_copy(uint32_t dst, const void* src,
                                          uint32_t bytes, uint32_t mbar) {
    asm volatile(
        "cp.async.bulk.shared::cluster.global.mbarrier::complete_tx::bytes "
        "[%0], [%1], %2, [%3];"
        :: "r"(dst), "l"(src), "r"(bytes), "r"(mbar) : "memory");
}
__device__ __forceinline__ void bulk_prefetch_l2(const void* src, uint32_t bytes) {
    asm volatile("cp.async.bulk.prefetch.L2.global [%0], %1;"
                 :: "l"(src), "r"(bytes));
}

// One 16-step chunk of the recurrence. GUARD=true only for the final chunk.
template <bool GUARD>
__device__ __forceinline__ void consume_chunk(
    const char* sb, const int* offb, const float* skipf,
    float a[5], int& E, int tbase, int lane, int lm1)
{
    const unsigned FULL = 0xFFFFFFFFu;
    const char* gp0 = sb + offb[0];
    const char* gp1 = sb + offb[1];
    const char* gp2 = sb + offb[2];
    const char* gp3 = sb + offb[3];
    const char* gp4 = sb + offb[4];

    float p[5];
    p[0] = *(const float*)(gp0);
    p[1] = *(const float*)(gp1);
    p[2] = *(const float*)(gp2);
    p[3] = *(const float*)(gp3);
    p[4] = *(const float*)(gp4);

#pragma unroll
    for (int g = 0; g < RPC / 4; g++) {
        // max at group start (lagged one group) via single REDUX (alphas >= 0
        // so uint order == float order); exact pow-2 scale applied at group
        // end, target biased to 2^40 (keeps working range above FTZ).
        float ml = fmaxf(fmaxf(fmaxf(a[0], a[1]), fmaxf(a[2], a[3])), a[4]);
        unsigned um = __reduce_max_sync(FULL, __float_as_uint(ml));

#pragma unroll
        for (int i = 0; i < 4; i++) {
            int j = g * 4 + i;
            int t = tbase + j;
            if (!GUARD || t < TT) {
                bool pf = (j + 1 < RPC) && (!GUARD || (t + 1 < TT));
                float np[5];
                if (pf) {
                    int ro = (j + 1) * CC * 4;
                    np[0] = *(const float*)(gp0 + ro);
                    np[1] = *(const float*)(gp1 + ro);
                    np[2] = *(const float*)(gp2 + ro);
                    np[3] = *(const float*)(gp3 + ro);
                    np[4] = *(const float*)(gp4 + ro);
                }
                // 2 shuffles/step: neighbor's a[4], a[3]
                float A4 = __shfl_sync(FULL, a[4], lm1);
                float A3 = __shfl_sync(FULL, a[3], lm1);
                if (lane == 0) { A4 = 0.0f; A3 = 0.0f; }

                float s0 = a[0] + A4   + skipf[0] * A3;
                float s1 = a[1] + a[0] + skipf[1] * A4;
                float s2 = a[2] + a[1] + skipf[2] * a[0];
                float s3 = a[3] + a[2] + skipf[3] * a[1];
                float s4 = a[4] + a[3] + skipf[4] * a[2];
                a[0] = s0 * p[0];
                a[1] = s1 * p[1];
                a[2] = s2 * p[2];
                a[3] = s3 * p[3];
                a[4] = s4 * p[4];
                if (pf) {
#pragma unroll
                    for (int k = 0; k < 5; k++) p[k] = np[k];
                }
            }
        }
        {
            int e = (int)((um >> 23) & 255u);
            int f = 294 - e;                    // exp field of 2^(167-e)
            if (f > 254) f = 254;
            if (f < 1)   f = 1;
            float sc = __int_as_float(f << 23); // exact power of 2
            E -= (f - 127);
#pragma unroll
            for (int k = 0; k < 5; k++) a[k] *= sc;
        }
    }
}

__global__ __launch_bounds__(WPB * 32, 1)
void ctc_pf_kernel(const int* __restrict__ y_true,
                   const float* __restrict__ y_pred,
                   float* __restrict__ out)
{
    extern __shared__ __align__(16) unsigned char smem_raw_[];
    const int tid  = threadIdx.x;
    const int wid  = tid >> 5;
    const int lane = tid & 31;
    const unsigned FULL = 0xFFFFFFFFu;

    const int b = wid * GRID + blockIdx.x;    // spread batches over all SMs
    if (b >= BB) return;                       // 80 tail warps idle

    float* rawb = (float*)smem_raw_ + wid * WARP_FLOATS;
    unsigned long long* mbar_s =
        (unsigned long long*)(smem_raw_ + WPB * WARP_FLOATS * 4) + wid * NSTG;

    const float* __restrict__ yp  = y_pred + (size_t)b * TT * CC;
    const int*   __restrict__ lab = y_true + b * LL;

    // ---- static per-(lane,k) metadata, lane-major: s = 5*lane + k ----
    int   offb[5];               // byte offsets into a row
    float skipf[5];
#pragma unroll
    for (int k = 0; k < 5; k++) {
        int s = 5 * lane + k;
        if (s < SS && (s & 1)) {
            int idx = (s - 1) >> 1;
            int cl  = lab[idx];
            offb[k] = cl * 4;
            skipf[k] = (idx > 0 && cl != lab[idx - 1]) ? 1.0f : 0.0f;
        } else {
            offb[k] = (CC - 1) * 4;   // blank / safe dummy for invalid s
            skipf[k] = 0.0f;
        }
    }

    // ---- t = 0 init: states 0 (blank) and 1 (label 0) live on lane 0 ----
    float a[5];
#pragma unroll
    for (int k = 0; k < 5; k++) a[k] = 0.0f;
    if (lane == 0) {
        a[0] = yp[CC - 1]  + EPSF;
        a[1] = yp[lab[0]] + EPSF;
    }

    // ---- prologue: barriers, NSTG stage fills, PFD chunks L2-prefetched ----
    if (lane == 0) {
#pragma unroll
        for (int s = 0; s < NSTG; s++) mbar_init(smem_u32(&mbar_s[s]), 1);
        asm volatile("fence.proxy.async.shared::cta;" ::: "memory");
#pragma unroll
        for (int c0 = 0; c0 < NSTG; c0++) {
            int t0   = 1 + RPC * c0;
            int rows = (TT - t0 < RPC) ? (TT - t0) : RPC;
            uint32_t bytes = (uint32_t)rows * CC * 4;
            mbar_expect_tx(smem_u32(&mbar_s[c0]), bytes);
            bulk_copy(smem_u32(rawb + c0 * STAGE_FLOATS), yp + (size_t)t0 * CC,
                      bytes, smem_u32(&mbar_s[c0]));
        }
#pragma unroll
        for (int c0 = NSTG; c0 < NSTG + PFD; c0++) {
            int t0   = 1 + RPC * c0;
            int rows = (TT - t0 < RPC) ? (TT - t0) : RPC;
            bulk_prefetch_l2(yp + (size_t)t0 * CC, (uint32_t)rows * CC * 4);
        }
    }
    __syncwarp();

    int E = 0;
    int buf = 0, trip = 0;
    const int lm1 = (lane + 31) & 31;

#pragma unroll 1
    for (int c = 0; c < NCH - 1; c++) {       // 31 full guard-free chunks
        const uint32_t mbadr = smem_u32(&mbar_s[buf]);

        // stage chunk c+NSTG+PFD into L2 (bulk path, fire-and-forget)
        {
            int cp = c + NSTG + PFD;
            if (cp < NCH && lane == 0) {
                int t0p   = 1 + RPC * cp;
                int rowsp = (TT - t0p < RPC) ? (TT - t0p) : RPC;
                bulk_prefetch_l2(yp + (size_t)t0p * CC,
                                 (uint32_t)rowsp * CC * 4);
            }
        }

        mbar_wait(mbadr, trip);

        consume_chunk<false>((const char*)(rawb + buf * STAGE_FLOATS),
                             offb, skipf, a, E, 1 + RPC * c, lane, lm1);

        __syncwarp();
        int cn = c + NSTG;
        if (cn < NCH && lane == 0) {
            int t0   = 1 + RPC * cn;
            int rows = (TT - t0 < RPC) ? (TT - t0) : RPC;
            uint32_t bytes = (uint32_t)rows * CC * 4;
            mbar_expect_tx(mbadr, bytes);
            bulk_copy(smem_u32(rawb + buf * STAGE_FLOATS), yp + (size_t)t0 * CC,
                      bytes, mbadr);
        }
        if (++buf == NSTG) { buf = 0; trip ^= 1; }
    }

    // ---- last (short) chunk, with bounds guards ----
    {
        const uint32_t mbadr = smem_u32(&mbar_s[buf]);
        mbar_wait(mbadr, trip);
        consume_chunk<true>((const char*)(rawb + buf * STAGE_FLOATS),
                            offb, skipf, a, E, 1 + RPC * (NCH - 1), lane, lm1);
    }

    // ---- loss: states 127,128 live on lane 25 (k=2, k=3) ----
    float v127 = __shfl_sync(FULL, a[2], 25);
    float v128 = __shfl_sync(FULL, a[3], 25);
    if (lane == 0)
        out[b] = -(logf(v127 + v128) + (float)E * 0.69314718055994530942f);
}

extern "C" void kernel_launch(void* const* d_in, const int* in_sizes, int n_in,
                              void* d_out, int out_size)
{
    const int*   y_true;
    const float* y_pred;
    if (in_sizes[0] == BB * LL) {
        y_true = (const int*)d_in[0];
        y_pred = (const float*)d_in[1];
    } else {
        y_true = (const int*)d_in[1];
        y_pred = (const float*)d_in[0];
    }
    float* out = (float*)d_out;

    cudaFuncSetAttribute(ctc_pf_kernel,
                         cudaFuncAttributeMaxDynamicSharedMemorySize,
                         SMEM_BYTES);
    ctc_pf_kernel<<<GRID, WPB * 32, SMEM_BYTES>>>(y_true, y_pred, out);
}

// round 15
// speedup vs baseline: 1.0861x; 1.0861x over previous
#include <cuda_runtime.h>
#include <cstdint>

// CTC loss (scaled forward algorithm, linear domain).
// B=512, T=512, C=256, L=64, S=129, blank = C-1.
// 148 blocks x 4 warps: warp w of block i processes batch b = w*148+i
// (b >= 512 -> idle), so all 148 SMs' TMA/L1TEX slices carry streams.
// Per warp: private 7-stage x 8-row TMA ring (56KB -> 224KB/block) to
// maximize in-flight bulk-copy bytes (BW = outstanding / latency).
// Lane-major state map s = 5*lane + k (2 shuffles/step), REDUX exact pow-2
// rescale per 4 steps (lagged one group, target biased 2^40). Last chunk
// peeled so main chunks run guard-free.

#define TT 512
#define CC 256
#define BB 512
#define LL 64
#define SS 129
#define EPSF 1e-7f
#define RPC 8                  // rows (timesteps) per stage
#define NSTG 7                 // ring stages per warp
#define NCH 64                 // chunks covering t = 1 .. 511 (last short)
#define WPB 4                  // warps per block
#define GRID 148
#define STAGE_FLOATS (RPC * CC)
#define WARP_FLOATS (NSTG * STAGE_FLOATS)
#define SMEM_BYTES (WPB * WARP_FLOATS * 4 + WPB * NSTG * 8 + 16)

__device__ __forceinline__ uint32_t smem_u32(const void* p) {
    uint32_t a;
    asm("{ .reg .u64 t; cvta.to.shared.u64 t, %1; cvt.u32.u64 %0, t; }"
        : "=r"(a) : "l"(p));
    return a;
}
__device__ __forceinline__ void mbar_init(uint32_t addr, uint32_t cnt) {
    asm volatile("mbarrier.init.shared.b64 [%0], %1;" :: "r"(addr), "r"(cnt) : "memory");
}
__device__ __forceinline__ void mbar_expect_tx(uint32_t addr, uint32_t bytes) {
    asm volatile("mbarrier.arrive.expect_tx.shared.b64 _, [%0], %1;"
                 :: "r"(addr), "r"(bytes) : "memory");
}
__device__ __forceinline__ void mbar_wait(uint32_t addr, uint32_t parity) {
    asm volatile(
        "{\n\t.reg .pred P;\n\t"
        "LAB_WAIT_%=:\n\t"
        "mbarrier.try_wait.parity.acquire.cta.shared::cta.b64 P, [%0], %1, 0x989680;\n\t"
        "@P bra.uni LAB_DONE_%=;\n\t"
        "bra.uni LAB_WAIT_%=;\n\t"
        "LAB_DONE_%=:\n\t}"
        :: "r"(addr), "r"(parity) : "memory");
}
__device__ __forceinline__ void bulk_copy(uint32_t dst, const void* src,
                                          uint32_t bytes, uint32_t mbar) {
    asm volatile(
        "cp.async.bulk.shared::cluster.global.mbarrier::complete_tx::bytes "
        "[%0], [%1], %2, [%3];"
        :: "r"(dst), "l"(src), "r"(bytes), "r"(mbar) : "memory");
}

// One RPC-step chunk of the recurrence. GUARD=true only for the final chunk.
template <bool GUARD>
__device__ __forceinline__ void consume_chunk(
    const char* sb, const int* offb, const float* skipf,
    float a[5], int& E, int tbase, int lane, int lm1)
{
    const unsigned FULL = 0xFFFFFFFFu;
    const char* gp0 = sb + offb[0];
    const char* gp1 = sb + offb[1];
    const char* gp2 = sb + offb[2];
    const char* gp3 = sb + offb[3];
    const char* gp4 = sb + offb[4];

    float p[5];
    p[0] = *(const float*)(gp0);
    p[1] = *(const float*)(gp1);
    p[2] = *(const float*)(gp2);
    p[3] = *(const float*)(gp3);
    p[4] = *(const float*)(gp4);

#pragma unroll
    for (int g = 0; g < RPC / 4; g++) {
        // max at group start (lagged one group) via single REDUX (alphas >= 0
        // so uint order == float order); exact pow-2 scale applied at group
        // end, target biased to 2^40 (keeps working range above FTZ).
        float ml = fmaxf(fmaxf(fmaxf(a[0], a[1]), fmaxf(a[2], a[3])), a[4]);
        unsigned um = __reduce_max_sync(FULL, __float_as_uint(ml));

#pragma unroll
        for (int i = 0; i < 4; i++) {
            int j = g * 4 + i;
            int t = tbase + j;
            if (!GUARD || t < TT) {
                bool pf = (j + 1 < RPC) && (!GUARD || (t + 1 < TT));
                float np[5];
                if (pf) {
                    int ro = (j + 1) * CC * 4;
                    np[0] = *(const float*)(gp0 + ro);
                    np[1] = *(const float*)(gp1 + ro);
                    np[2] = *(const float*)(gp2 + ro);
                    np[3] = *(const float*)(gp3 + ro);
                    np[4] = *(const float*)(gp4 + ro);
                }
                // 2 shuffles/step: neighbor's a[4], a[3]
                float A4 = __shfl_sync(FULL, a[4], lm1);
                float A3 = __shfl_sync(FULL, a[3], lm1);
                if (lane == 0) { A4 = 0.0f; A3 = 0.0f; }

                float s0 = a[0] + A4   + skipf[0] * A3;
                float s1 = a[1] + a[0] + skipf[1] * A4;
                float s2 = a[2] + a[1] + skipf[2] * a[0];
                float s3 = a[3] + a[2] + skipf[3] * a[1];
                float s4 = a[4] + a[3] + skipf[4] * a[2];
                a[0] = s0 * p[0];
                a[1] = s1 * p[1];
                a[2] = s2 * p[2];
                a[3] = s3 * p[3];
                a[4] = s4 * p[4];
                if (pf) {
#pragma unroll
                    for (int k = 0; k < 5; k++) p[k] = np[k];
                }
            }
        }
        {
            int e = (int)((um >> 23) & 255u);
            int f = 294 - e;                    // exp field of 2^(167-e)
            if (f > 254) f = 254;
            if (f < 1)   f = 1;
            float sc = __int_as_float(f << 23); // exact power of 2
            E -= (f - 127);
#pragma unroll
            for (int k = 0; k < 5; k++) a[k] *= sc;
        }
    }
}

__global__ __launch_bounds__(WPB * 32, 1)
void ctc_deep_kernel(const int* __restrict__ y_true,
                     const float* __restrict__ y_pred,
                     float* __restrict__ out)
{
    extern __shared__ __align__(16) unsigned char smem_raw_[];
    const int tid  = threadIdx.x;
    const int wid  = tid >> 5;
    const int lane = tid & 31;
    const unsigned FULL = 0xFFFFFFFFu;

    const int b = wid * GRID + blockIdx.x;    // spread batches over all SMs
    if (b >= BB) return;                       // 80 tail warps idle

    float* rawb = (float*)smem_raw_ + wid * WARP_FLOATS;
    unsigned long long* mbar_s =
        (unsigned long long*)(smem_raw_ + WPB * WARP_FLOATS * 4) + wid * NSTG;

    const float* __restrict__ yp  = y_pred + (size_t)b * TT * CC;
    const int*   __restrict__ lab = y_true + b * LL;

    // ---- static per-(lane,k) metadata, lane-major: s = 5*lane + k ----
    int   offb[5];               // byte offsets into a row
    float skipf[5];
#pragma unroll
    for (int k = 0; k < 5; k++) {
        int s = 5 * lane + k;
        if (s < SS && (s & 1)) {
            int idx = (s - 1) >> 1;
            int cl  = lab[idx];
            offb[k] = cl * 4;
            skipf[k] = (idx > 0 && cl != lab[idx - 1]) ? 1.0f : 0.0f;
        } else {
            offb[k] = (CC - 1) * 4;   // blank / safe dummy for invalid s
            skipf[k] = 0.0f;
        }
    }

    // ---- t = 0 init: states 0 (blank) and 1 (label 0) live on lane 0 ----
    float a[5];
#pragma unroll
    for (int k = 0; k < 5; k++) a[k] = 0.0f;
    if (lane == 0) {
        a[0] = yp[CC - 1]  + EPSF;
        a[1] = yp[lab[0]] + EPSF;
    }

    // ---- prologue: init own barriers, launch all NSTG stage fills ----
    if (lane == 0) {
#pragma unroll
        for (int s = 0; s < NSTG; s++) mbar_init(smem_u32(&mbar_s[s]), 1);
        asm volatile("fence.proxy.async.shared::cta;" ::: "memory");
#pragma unroll
        for (int c0 = 0; c0 < NSTG; c0++) {
            int t0   = 1 + RPC * c0;
            int rows = (TT - t0 < RPC) ? (TT - t0) : RPC;
            uint32_t bytes = (uint32_t)rows * CC * 4;
            mbar_expect_tx(smem_u32(&mbar_s[c0]), bytes);
            bulk_copy(smem_u32(rawb + c0 * STAGE_FLOATS), yp + (size_t)t0 * CC,
                      bytes, smem_u32(&mbar_s[c0]));
        }
    }
    __syncwarp();

    int E = 0;
    int buf = 0, trip = 0;
    const int lm1 = (lane + 31) & 31;

#pragma unroll 1
    for (int c = 0; c < NCH - 1; c++) {       // 63 full guard-free chunks
        const uint32_t mbadr = smem_u32(&mbar_s[buf]);
        mbar_wait(mbadr, trip);

        consume_chunk<false>((const char*)(rawb + buf * STAGE_FLOATS),
                             offb, skipf, a, E, 1 + RPC * c, lane, lm1);

        __syncwarp();
        int cn = c + NSTG;
        if (cn < NCH && lane == 0) {
            int t0   = 1 + RPC * cn;
            int rows = (TT - t0 < RPC) ? (TT - t0) : RPC;
            uint32_t bytes = (uint32_t)rows * CC * 4;
            mbar_expect_tx(mbadr, bytes);
            bulk_copy(smem_u32(rawb + buf * STAGE_FLOATS), yp + (size_t)t0 * CC,
                      bytes, mbadr);
        }
        if (++buf == NSTG) { buf = 0; trip ^= 1; }
    }

    // ---- last (short) chunk, with bounds guards ----
    {
        const uint32_t mbadr = smem_u32(&mbar_s[buf]);
        mbar_wait(mbadr, trip);
        consume_chunk<true>((const char*)(rawb + buf * STAGE_FLOATS),
                            offb, skipf, a, E, 1 + RPC * (NCH - 1), lane, lm1);
    }

    // ---- loss: states 127,128 live on lane 25 (k=2, k=3) ----
    float v127 = __shfl_sync(FULL, a[2], 25);
    float v128 = __shfl_sync(FULL, a[3], 25);
    if (lane == 0)
        out[b] = -(logf(v127 + v128) + (float)E * 0.69314718055994530942f);
}

extern "C" void kernel_launch(void* const* d_in, const int* in_sizes, int n_in,
                              void* d_out, int out_size)
{
    const int*   y_true;
    const float* y_pred;
    if (in_sizes[0] == BB * LL) {
        y_true = (const int*)d_in[0];
        y_pred = (const float*)d_in[1];
    } else {
        y_true = (const int*)d_in[1];
        y_pred = (const float*)d_in[0];
    }
    float* out = (float*)d_out;

    cudaFuncSetAttribute(ctc_deep_kernel,
                         cudaFuncAttributeMaxDynamicSharedMemorySize,
                         SMEM_BYTES);
    ctc_deep_kernel<<<GRID, WPB * 32, SMEM_BYTES>>>(y_true, y_pred, out);
}

// round 16
// speedup vs baseline: 1.1779x; 1.0846x over previous
#include <cuda_runtime.h>
#include <cstdint>

// CTC loss (scaled forward algorithm, linear domain).
// B=512, T=512, C=256, L=64, S=129, blank = C-1.
// 296 blocks x 2 warps (2 CTAs/SM): warp w of block i processes batch
// b = w*296 + i (b >= 512 -> idle). Tests whether TMA/mbarrier queueing is
// per-CTA (two CTAs/SM would then double effective supply).
// Per warp: private 3-stage x 16-row TMA ring (48KB), lane-major state map
// s = 5*lane + k (2 shuffles/step), REDUX exact pow-2 rescale per 4 steps
// (lagged one group, target biased 2^40). Last chunk peeled.

#define TT 512
#define CC 256
#define BB 512
#define LL 64
#define SS 129
#define EPSF 1e-7f
#define RPC 16                 // rows (timesteps) per stage
#define NSTG 3                 // ring stages per warp
#define NCH 32                 // chunks covering t = 1 .. 511 (last short)
#define WPB 2                  // warps per block
#define GRID 296
#define STAGE_FLOATS (RPC * CC)
#define WARP_FLOATS (NSTG * STAGE_FLOATS)
#define SMEM_BYTES (WPB * WARP_FLOATS * 4 + WPB * NSTG * 8 + 16)

__device__ __forceinline__ uint32_t smem_u32(const void* p) {
    uint32_t a;
    asm("{ .reg .u64 t; cvta.to.shared.u64 t, %1; cvt.u32.u64 %0, t; }"
        : "=r"(a) : "l"(p));
    return a;
}
__device__ __forceinline__ void mbar_init(uint32_t addr, uint32_t cnt) {
    asm volatile("mbarrier.init.shared.b64 [%0], %1;" :: "r"(addr), "r"(cnt) : "memory");
}
__device__ __forceinline__ void mbar_expect_tx(uint32_t addr, uint32_t bytes) {
    asm volatile("mbarrier.arrive.expect_tx.shared.b64 _, [%0], %1;"
                 :: "r"(addr), "r"(bytes) : "memory");
}
__device__ __forceinline__ void mbar_wait(uint32_t addr, uint32_t parity) {
    asm volatile(
        "{\n\t.reg .pred P;\n\t"
        "LAB_WAIT_%=:\n\t"
        "mbarrier.try_wait.parity.acquire.cta.shared::cta.b64 P, [%0], %1, 0x989680;\n\t"
        "@P bra.uni LAB_DONE_%=;\n\t"
        "bra.uni LAB_WAIT_%=;\n\t"
        "LAB_DONE_%=:\n\t}"
        :: "r"(addr), "r"(parity) : "memory");
}
__device__ __forceinline__ void bulk_copy(uint32_t dst, const void* src,
                                          uint32_t bytes, uint32_t mbar) {
    asm volatile(
        "cp.async.bulk.shared::cluster.global.mbarrier::complete_tx::bytes "
        "[%0], [%1], %2, [%3];"
        :: "r"(dst), "l"(src), "r"(bytes), "r"(mbar) : "memory");
}

// One RPC-step chunk of the recurrence. GUARD=true only for the final chunk.
template <bool GUARD>
__device__ __forceinline__ void consume_chunk(
    const char* sb, const int* offb, const float* skipf,
    float a[5], int& E, int tbase, int lane, int lm1)
{
    const unsigned FULL = 0xFFFFFFFFu;
    const char* gp0 = sb + offb[0];
    const char* gp1 = sb + offb[1];
    const char* gp2 = sb + offb[2];
    const char* gp3 = sb + offb[3];
    const char* gp4 = sb + offb[4];

    float p[5];
    p[0] = *(const float*)(gp0);
    p[1] = *(const float*)(gp1);
    p[2] = *(const float*)(gp2);
    p[3] = *(const float*)(gp3);
    p[4] = *(const float*)(gp4);

#pragma unroll
    for (int g = 0; g < RPC / 4; g++) {
        // max at group start (lagged one group) via single REDUX (alphas >= 0
        // so uint order == float order); exact pow-2 scale applied at group
        // end, target biased to 2^40 (keeps working range above FTZ).
        float ml = fmaxf(fmaxf(fmaxf(a[0], a[1]), fmaxf(a[2], a[3])), a[4]);
        unsigned um = __reduce_max_sync(FULL, __float_as_uint(ml));

#pragma unroll
        for (int i = 0; i < 4; i++) {
            int j = g * 4 + i;
            int t = tbase + j;
            if (!GUARD || t < TT) {
                bool pf = (j + 1 < RPC) && (!GUARD || (t + 1 < TT));
                float np[5];
                if (pf) {
                    int ro = (j + 1) * CC * 4;
                    np[0] = *(const float*)(gp0 + ro);
                    np[1] = *(const float*)(gp1 + ro);
                    np[2] = *(const float*)(gp2 + ro);
                    np[3] = *(const float*)(gp3 + ro);
                    np[4] = *(const float*)(gp4 + ro);
                }
                // 2 shuffles/step: neighbor's a[4], a[3]
                float A4 = __shfl_sync(FULL, a[4], lm1);
                float A3 = __shfl_sync(FULL, a[3], lm1);
                if (lane == 0) { A4 = 0.0f; A3 = 0.0f; }

                float s0 = a[0] + A4   + skipf[0] * A3;
                float s1 = a[1] + a[0] + skipf[1] * A4;
                float s2 = a[2] + a[1] + skipf[2] * a[0];
                float s3 = a[3] + a[2] + skipf[3] * a[1];
                float s4 = a[4] + a[3] + skipf[4] * a[2];
                a[0] = s0 * p[0];
                a[1] = s1 * p[1];
                a[2] = s2 * p[2];
                a[3] = s3 * p[3];
                a[4] = s4 * p[4];
                if (pf) {
#pragma unroll
                    for (int k = 0; k < 5; k++) p[k] = np[k];
                }
            }
        }
        {
            int e = (int)((um >> 23) & 255u);
            int f = 294 - e;                    // exp field of 2^(167-e)
            if (f > 254) f = 254;
            if (f < 1)   f = 1;
            float sc = __int_as_float(f << 23); // exact power of 2
            E -= (f - 127);
#pragma unroll
            for (int k = 0; k < 5; k++) a[k] *= sc;
        }
    }
}

__global__ __launch_bounds__(WPB * 32, 2)
void ctc_2cta_kernel(const int* __restrict__ y_true,
                     const float* __restrict__ y_pred,
                     float* __restrict__ out)
{
    extern __shared__ __align__(16) unsigned char smem_raw_[];
    const int tid  = threadIdx.x;
    const int wid  = tid >> 5;
    const int lane = tid & 31;
    const unsigned FULL = 0xFFFFFFFFu;

    const int b = wid * GRID + blockIdx.x;    // spread batches over all SMs
    if (b >= BB) return;                       // 80 tail warps idle

    float* rawb = (float*)smem_raw_ + wid * WARP_FLOATS;
    unsigned long long* mbar_s =
        (unsigned long long*)(smem_raw_ + WPB * WARP_FLOATS * 4) + wid * NSTG;

    const float* __restrict__ yp  = y_pred + (size_t)b * TT * CC;
    const int*   __restrict__ lab = y_true + b * LL;

    // ---- static per-(lane,k) metadata, lane-major: s = 5*lane + k ----
    int   offb[5];               // byte offsets into a row
    float skipf[5];
#pragma unroll
    for (int k = 0; k < 5; k++) {
        int s = 5 * lane + k;
        if (s < SS && (s & 1)) {
            int idx = (s - 1) >> 1;
            int cl  = lab[idx];
            offb[k] = cl * 4;
            skipf[k] = (idx > 0 && cl != lab[idx - 1]) ? 1.0f : 0.0f;
        } else {
            offb[k] = (CC - 1) * 4;   // blank / safe dummy for invalid s
            skipf[k] = 0.0f;
        }
    }

    // ---- t = 0 init: states 0 (blank) and 1 (label 0) live on lane 0 ----
    float a[5];
#pragma unroll
    for (int k = 0; k < 5; k++) a[k] = 0.0f;
    if (lane == 0) {
        a[0] = yp[CC - 1]  + EPSF;
        a[1] = yp[lab[0]] + EPSF;
    }

    // ---- prologue: init own barriers, launch all NSTG stage fills ----
    if (lane == 0) {
#pragma unroll
        for (int s = 0; s < NSTG; s++) mbar_init(smem_u32(&mbar_s[s]), 1);
        asm volatile("fence.proxy.async.shared::cta;" ::: "memory");
#pragma unroll
        for (int c0 = 0; c0 < NSTG; c0++) {
            int t0   = 1 + RPC * c0;
            int rows = (TT - t0 < RPC) ? (TT - t0) : RPC;
            uint32_t bytes = (uint32_t)rows * CC * 4;
            mbar_expect_tx(smem_u32(&mbar_s[c0]), bytes);
            bulk_copy(smem_u32(rawb + c0 * STAGE_FLOATS), yp + (size_t)t0 * CC,
                      bytes, smem_u32(&mbar_s[c0]));
        }
    }
    __syncwarp();

    int E = 0;
    int buf = 0, trip = 0;
    const int lm1 = (lane + 31) & 31;

#pragma unroll 1
    for (int c = 0; c < NCH - 1; c++) {       // 31 full guard-free chunks
        const uint32_t mbadr = smem_u32(&mbar_s[buf]);
        mbar_wait(mbadr, trip);

        consume_chunk<false>((const char*)(rawb + buf * STAGE_FLOATS),
                             offb, skipf, a, E, 1 + RPC * c, lane, lm1);

        __syncwarp();
        int cn = c + NSTG;
        if (cn < NCH && lane == 0) {
            int t0   = 1 + RPC * cn;
            int rows = (TT - t0 < RPC) ? (TT - t0) : RPC;
            uint32_t bytes = (uint32_t)rows * CC * 4;
            mbar_expect_tx(mbadr, bytes);
            bulk_copy(smem_u32(rawb + buf * STAGE_FLOATS), yp + (size_t)t0 * CC,
                      bytes, mbadr);
        }
        if (++buf == NSTG) { buf = 0; trip ^= 1; }
    }

    // ---- last (short) chunk, with bounds guards ----
    {
        const uint32_t mbadr = smem_u32(&mbar_s[buf]);
        mbar_wait(mbadr, trip);
        consume_chunk<true>((const char*)(rawb + buf * STAGE_FLOATS),
                            offb, skipf, a, E, 1 + RPC * (NCH - 1), lane, lm1);
    }

    // ---- loss: states 127,128 live on lane 25 (k=2, k=3) ----
    float v127 = __shfl_sync(FULL, a[2], 25);
    float v128 = __shfl_sync(FULL, a[3], 25);
    if (lane == 0)
        out[b] = -(logf(v127 + v128) + (float)E * 0.69314718055994530942f);
}

extern "C" void kernel_launch(void* const* d_in, const int* in_sizes, int n_in,
                              void* d_out, int out_size)
{
    const int*   y_true;
    const float* y_pred;
    if (in_sizes[0] == BB * LL) {
        y_true = (const int*)d_in[0];
        y_pred = (const float*)d_in[1];
    } else {
        y_true = (const int*)d_in[1];
        y_pred = (const float*)d_in[0];
    }
    float* out = (float*)d_out;

    cudaFuncSetAttribute(ctc_2cta_kernel,
                         cudaFuncAttributeMaxDynamicSharedMemorySize,
                         SMEM_BYTES);
    ctc_2cta_kernel<<<GRID, WPB * 32, SMEM_BYTES>>>(y_true, y_pred, out);
}